// round 13
// baseline (speedup 1.0000x reference)
#include <cuda_runtime.h>
#include <cuda_bf16.h>
#include <cuda_fp16.h>
#include <cstdint>
#include <cstddef>

// Problem constants
#define PB 4
#define PS 2048
#define PD 1024
#define PH 16
#define PHD 64
#define PM (PB * PS)
#define GK 1024

// ---------------------------------------------------------------------------
// Scratch (device globals; allocation-free)
// ---------------------------------------------------------------------------
__device__ __half g_Qh[PB * PH * PS * PHD];   // Q fp16, scale*log2e folded
__device__ __half g_Kh[PB * PH * PS * PHD];   // K fp16 [B,H,S,HD]
__device__ __half g_Vh[PB * PH * PHD * PS];   // V fp16 [B,H,HD,S]
__device__ __half g_Of[PB * PS * PD];         // attn out fp16
__device__ __half g_Af[3][PM * GK];           // activations fp16
__device__ __half g_Wf[4][PD * GK];           // weights fp16

extern __shared__ char dynsm[];

// ---------------------------------------------------------------------------
// helpers
// ---------------------------------------------------------------------------
__device__ __forceinline__ uint32_t smem_to_u32(const void* p) {
    uint32_t a;
    asm("{ .reg .u64 t; cvta.to.shared.u64 t, %1; cvt.u32.u64 %0, t; }"
        : "=r"(a) : "l"(p));
    return a;
}

__device__ __forceinline__ void ldsm4(uint32_t* r, uint32_t addr) {
    asm volatile("ldmatrix.sync.aligned.m8n8.x4.shared.b16 {%0,%1,%2,%3}, [%4];"
                 : "=r"(r[0]), "=r"(r[1]), "=r"(r[2]), "=r"(r[3]) : "r"(addr));
}

__device__ __forceinline__ void mma_f16(float* c, const uint32_t* a,
                                        const uint32_t* b) {
    asm volatile(
        "mma.sync.aligned.m16n8k16.row.col.f32.f16.f16.f32 "
        "{%0,%1,%2,%3}, {%4,%5,%6,%7}, {%8,%9}, {%0,%1,%2,%3};"
        : "+f"(c[0]), "+f"(c[1]), "+f"(c[2]), "+f"(c[3])
        : "r"(a[0]), "r"(a[1]), "r"(a[2]), "r"(a[3]), "r"(b[0]), "r"(b[1]));
}

__device__ __forceinline__ void cp16(uint32_t dst, const void* src) {
    asm volatile("cp.async.cg.shared.global [%0], [%1], 16;"
                 :: "r"(dst), "l"(src) : "memory");
}
#define CP_COMMIT() asm volatile("cp.async.commit_group;" ::: "memory")
#define CP_WAIT(N)  asm volatile("cp.async.wait_group %0;" :: "n"(N) : "memory")

// ---------------------------------------------------------------------------
// presplit: fp32 -> fp16
// ---------------------------------------------------------------------------
__global__ __launch_bounds__(256) void presplitA3_kernel(
    const float* __restrict__ X0, const float* __restrict__ X1,
    const float* __restrict__ X2, __half* __restrict__ F, int n4)
{
    const int z = blockIdx.y;
    const float* X = (z == 0) ? X0 : (z == 1) ? X1 : X2;
    __half* Xf = F + (size_t)z * PM * GK;
    int i = blockIdx.x * blockDim.x + threadIdx.x;
    if (i < n4) {
        float4 v = ((const float4*)X)[i];
        __half2 a = __floats2half2_rn(v.x, v.y);
        __half2 b = __floats2half2_rn(v.z, v.w);
        uint2 o; o.x = *(uint32_t*)&a; o.y = *(uint32_t*)&b;
        ((uint2*)Xf)[i] = o;
    }
}

__global__ __launch_bounds__(256) void presplitW4_kernel(
    const float* __restrict__ X0, const float* __restrict__ X1,
    const float* __restrict__ X2, const float* __restrict__ X3,
    __half* __restrict__ F, int n4)
{
    const int z = blockIdx.y;
    const float* X = (z == 0) ? X0 : (z == 1) ? X1 : (z == 2) ? X2 : X3;
    __half* Xf = F + (size_t)z * PD * GK;
    int i = blockIdx.x * blockDim.x + threadIdx.x;
    if (i < n4) {
        float4 v = ((const float4*)X)[i];
        __half2 a = __floats2half2_rn(v.x, v.y);
        __half2 b = __floats2half2_rn(v.z, v.w);
        uint2 o; o.x = *(uint32_t*)&a; o.y = *(uint32_t*)&b;
        ((uint2*)Xf)[i] = o;
    }
}

// ---------------------------------------------------------------------------
// GEMM core: pure fp16, K-chunk 64, cp.async 3-stage pipeline. (unchanged R12)
// mode 0: fp32 C[m][n]; mode 1: fp16 [B,H,S,HD]; mode 2: fp16 [B,H,HD,S]
// ---------------------------------------------------------------------------
#define RS 72
#define STAGE_R 18432                  // 128 * 72 * 2
#define GEMM_STAGE (2 * STAGE_R)       // A | W = 36864
#define GEMM_SMEM (3 * GEMM_STAGE)     // 110592
#define NCHUNK 16

__device__ __forceinline__ void gemm_core(
    const __half* __restrict__ A, const __half* __restrict__ W,
    const float* __restrict__ bias, float* __restrict__ C,
    __half* __restrict__ Cf, int mode, float scale, int m0, int n0)
{
    const int tid = threadIdx.x;
    const int wid = tid >> 5;
    const int lane = tid & 31;
    const int wm = (wid & 1) * 64;
    const int wn = (wid >> 1) * 32;

    const uint32_t sb = smem_to_u32(dynsm);

    const int sub = lane >> 3;
    const int r8  = lane & 7;
    const int arow_in = (sub & 1) * 8 + r8;
    const int ak      = (sub >> 1) * 8;
    const int brow_in = (sub >> 1) * 8 + r8;
    const int bk      = (sub & 1) * 8;

    float acc[4][4][4];
#pragma unroll
    for (int i = 0; i < 4; i++)
#pragma unroll
        for (int j = 0; j < 4; j++)
#pragma unroll
            for (int q = 0; q < 4; q++) acc[i][j][q] = 0.0f;

    auto fetch = [&](int c, int s) {
        const uint32_t stg = sb + s * GEMM_STAGE;
        const int k0 = c * 64;
#pragma unroll
        for (int i = 0; i < 4; i++) {
            int id = tid + i * 256;
            int row = id >> 3;
            int ch  = (id & 7) * 8;
            uint32_t so = stg + (uint32_t)(row * RS + ch) * 2;
            cp16(so,           A + (size_t)(m0 + row) * GK + k0 + ch);
            cp16(so + STAGE_R, W + (size_t)(n0 + row) * GK + k0 + ch);
        }
    };

    fetch(0, 0); CP_COMMIT();
    fetch(1, 1); CP_COMMIT();

    int s = 0;
    for (int c = 0; c < NCHUNK; c++) {
        if (c + 1 < NCHUNK) { CP_WAIT(1); } else { CP_WAIT(0); }
        __syncthreads();
        if (c + 2 < NCHUNK) {
            int s2 = s + 2; if (s2 >= 3) s2 -= 3;
            fetch(c + 2, s2);
            CP_COMMIT();
        }

        const uint32_t stg = sb + s * GEMM_STAGE;
#pragma unroll
        for (int ks = 0; ks < 64; ks += 16) {
            uint32_t a4[4][4];
#pragma unroll
            for (int mt = 0; mt < 4; mt++) {
                uint32_t aoff = (uint32_t)((wm + mt * 16 + arow_in) * RS + ks + ak) * 2;
                ldsm4(a4[mt], stg + aoff);
            }
#pragma unroll
            for (int nb = 0; nb < 2; nb++) {
                uint32_t b4[4];
                uint32_t boff = (uint32_t)((wn + nb * 16 + brow_in) * RS + ks + bk) * 2;
                ldsm4(b4, stg + STAGE_R + boff);
#pragma unroll
                for (int mt = 0; mt < 4; mt++) {
                    mma_f16(acc[mt][nb * 2],     a4[mt], &b4[0]);
                    mma_f16(acc[mt][nb * 2 + 1], a4[mt], &b4[2]);
                }
            }
        }
        if (++s >= 3) s -= 3;
    }

    // ---- epilogue ----
    const int g = lane >> 2;
    const int tq = lane & 3;
#pragma unroll
    for (int n8 = 0; n8 < 4; n8++) {
        const int n = n0 + wn + n8 * 8 + 2 * tq;
        const float b0 = __ldg(&bias[n]);
        const float b1 = __ldg(&bias[n + 1]);
        const int h = n >> 6, hd = n & (PHD - 1);
#pragma unroll
        for (int mt = 0; mt < 4; mt++) {
            int m1 = m0 + wm + mt * 16 + g;
            int m2 = m1 + 8;
            float v00 = acc[mt][n8][0] + b0, v01 = acc[mt][n8][1] + b1;
            float v10 = acc[mt][n8][2] + b0, v11 = acc[mt][n8][3] + b1;
            if (mode == 0) {
                *(float2*)&C[(size_t)m1 * PD + n] = make_float2(v00, v01);
                *(float2*)&C[(size_t)m2 * PD + n] = make_float2(v10, v11);
            } else {
                int b1i = m1 >> 11, s1 = m1 & (PS - 1);
                int b2i = m2 >> 11, s2 = m2 & (PS - 1);
                __half2 q1 = __floats2half2_rn(v00 * scale, v01 * scale);
                __half2 q2 = __floats2half2_rn(v10 * scale, v11 * scale);
                if (mode == 1) {
                    size_t i1 = ((size_t)(b1i * PH + h) * PS + s1) * PHD + hd;
                    size_t i2 = ((size_t)(b2i * PH + h) * PS + s2) * PHD + hd;
                    *(uint32_t*)&Cf[i1] = *(uint32_t*)&q1;
                    *(uint32_t*)&Cf[i2] = *(uint32_t*)&q2;
                } else {
                    size_t base1 = ((size_t)(b1i * PH + h) * PHD + hd) * PS + s1;
                    size_t base2 = ((size_t)(b2i * PH + h) * PHD + hd) * PS + s2;
                    Cf[base1]      = q1.x;
                    Cf[base1 + PS] = q1.y;
                    Cf[base2]      = q2.x;
                    Cf[base2 + PS] = q2.y;
                }
            }
        }
    }
}

__global__ __launch_bounds__(256, 2) void qkv_gemm_kernel(
    const __half* __restrict__ Abase, const __half* __restrict__ Wbase,
    const float* __restrict__ bq, const float* __restrict__ bk,
    const float* __restrict__ bv,
    __half* __restrict__ qh, __half* __restrict__ kh, __half* __restrict__ vh)
{
    const int z = blockIdx.z;
    const __half* A = Abase + (size_t)z * PM * GK;
    const __half* W = Wbase + (size_t)z * PD * GK;
    const float* bias = (z == 0) ? bq : (z == 1) ? bk : bv;
    __half* Cf = (z == 0) ? qh : (z == 1) ? kh : vh;
    const int mode = (z == 2) ? 2 : 1;
    const float scale = (z == 0) ? 0.18033688011112042f : 1.0f;  // log2(e)/8
    gemm_core(A, W, bias, nullptr, Cf, mode, scale,
              blockIdx.y * 128, blockIdx.x * 128);
}

__global__ __launch_bounds__(256, 2) void out_gemm_kernel(
    const __half* __restrict__ A, const __half* __restrict__ W,
    const float* __restrict__ bias, float* __restrict__ C)
{
    gemm_core(A, W, bias, C, nullptr, 0, 1.0f,
              blockIdx.y * 128, blockIdx.x * 128);
}

// ---------------------------------------------------------------------------
// Tensor-core causal flash attention, fp16, fixed-C softmax.
// Paired k-tiles: each pipeline stage holds TWO (K|V) subtile blocks ->
// one __syncthreads per 128 k-cols and 2-tile prefetch distance.
// l computed via MMA against ones-row (V rows 64..79).
// ---------------------------------------------------------------------------
#define ARS 72
#define KREG 9216                    // K: 64 rows * 72 * 2
#define VREG 11520                   // V: 80 rows * 72 * 2 (incl. ones block)
#define ASUB (KREG + VREG)           // one k-subtile block: 20736
#define ASTG (2 * ASUB)              // stage = 2 subtiles: 41472
#define ATTN_SMEM (2 * ASTG)         // 82944
#define SOFTC 6.0f

__global__ __launch_bounds__(256, 2) void attn_mma_kernel(
    const __half* __restrict__ Qh,
    const __half* __restrict__ Kh, const __half* __restrict__ Vh,
    __half* __restrict__ Of)
{
    const uint32_t sb = smem_to_u32(dynsm);

    const int qi = blockIdx.x;
    const int h  = blockIdx.y;
    const int b  = blockIdx.z;
    const int tid = threadIdx.x;
    const int w = tid >> 5;
    const int lane = tid & 31;

    const int sub = lane >> 3;
    const int r8  = lane & 7;
    const int arow_in = (sub & 1) * 8 + r8;
    const int ak      = (sub >> 1) * 8;
    const int brow_in = (sub >> 1) * 8 + r8;
    const int bk      = (sub & 1) * 8;
    const int g  = lane >> 2;
    const int tq = lane & 3;

    const size_t bh = (size_t)(b * PH + h);
    const __half* qhp = Qh + (bh * PS + qi * 128) * PHD;
    const __half* khp = Kh + bh * PS * PHD;
    const __half* vhp = Vh + bh * PHD * PS;

    // ---- prologue: stage Q in bytes [0,18432) of stage0/sub0 (K region +
    // V data rows; disjoint from all ones regions which sit at
    // sub-offset KREG + 64*144 = 18432..20736 within each subtile block) ----
#pragma unroll
    for (int i = 0; i < 4; i++) {
        int fid = tid + i * 256;
        int row = fid >> 3;
        int c8  = (fid & 7) * 8;
        *(uint4*)(dynsm + (row * ARS + c8) * 2) =
            *(const uint4*)(qhp + row * PHD + c8);
    }
    // init ones/zero rows for all 4 subtile blocks (2 stages x 2 subs)
#pragma unroll
    for (int i = 0; i < 8; i++) {
        int id = tid + i * 256;          // 0..2047
        int blk = id >> 9;               // 0..3 (stage*2+sub)
        int rr  = (id >> 5) & 15;        // 0..15 -> V row 64+rr
        int cw  = id & 31;               // half2 word within row
        uint32_t val = (rr == 0) ? 0x3C003C00u : 0u;   // row 64 = 1.0
        *(uint32_t*)(dynsm + blk * ASUB + KREG + (64 + rr) * (ARS * 2) + cw * 4) = val;
    }
    __syncthreads();

    uint32_t qa[4][4];
#pragma unroll
    for (int s = 0; s < 4; s++) {
        uint32_t aoff = (uint32_t)((w * 16 + arow_in) * ARS + s * 16 + ak) * 2;
        ldsm4(qa[s], sb + aoff);
    }
    __syncthreads();

    const int qrow0 = qi * 128 + w * 16;
    float oc[8][4];
    float ocl[4];
#pragma unroll
    for (int j = 0; j < 8; j++)
#pragma unroll
        for (int q = 0; q < 4; q++) oc[j][q] = 0.0f;
#pragma unroll
    for (int q = 0; q < 4; q++) ocl[q] = 0.0f;

    // fetch one pair of k-subtiles (kt = 2p, 2p+1) into stage s
    auto fetchpair = [&](int p, int s) {
        const uint32_t stg = sb + s * ASTG;
#pragma unroll
        for (int su = 0; su < 2; su++) {
            const int kt = 2 * p + su;
            const uint32_t blk = stg + su * ASUB;
#pragma unroll
            for (int i = 0; i < 2; i++) {
                int id = tid + i * 256;
                int row = id >> 3;
                int ch = (id & 7) * 8;
                uint32_t so = blk + (uint32_t)(row * ARS + ch) * 2;
                cp16(so,        khp + (size_t)(kt * 64 + row) * PHD + ch);
                cp16(so + KREG, vhp + (size_t)row * PS + kt * 64 + ch);
            }
        }
    };

    const int npairs = qi + 1;           // ntiles = 2*qi+2, always even
    fetchpair(0, 0);
    CP_COMMIT();

    for (int p = 0; p < npairs; p++) {
        const int s = p & 1;
        CP_WAIT(0);
        __syncthreads();
        if (p + 1 < npairs) {
            fetchpair(p + 1, s ^ 1);
            CP_COMMIT();
        }

#pragma unroll
        for (int su = 0; su < 2; su++) {
            const int kt = 2 * p + su;
            if (kt * 64 > qrow0 + 15) break;     // later subtiles also masked
            const uint32_t stg = sb + s * ASTG + su * ASUB;

            // ---- S = Q @ K^T, accumulator pre-biased by -C ----
            float sc[8][4];
#pragma unroll
            for (int j = 0; j < 8; j++)
#pragma unroll
                for (int q = 0; q < 4; q++) sc[j][q] = -SOFTC;

#pragma unroll
            for (int ss = 0; ss < 4; ss++) {
#pragma unroll
                for (int nb = 0; nb < 4; nb++) {
                    uint32_t kh4[4];
                    uint32_t boff = (uint32_t)((nb * 16 + brow_in) * ARS + ss * 16 + bk) * 2;
                    ldsm4(kh4, stg + boff);
                    mma_f16(sc[nb * 2],     qa[ss], &kh4[0]);
                    mma_f16(sc[nb * 2 + 1], qa[ss], &kh4[2]);
                }
            }

            // ---- causal mask on diagonal tiles ----
            if (kt * 64 + 63 > qrow0) {
                const int rA = qrow0 + g, rB = rA + 8;
#pragma unroll
                for (int j = 0; j < 8; j++) {
                    int c = kt * 64 + j * 8 + 2 * tq;
                    if (c     > rA) sc[j][0] = -1e30f;
                    if (c + 1 > rA) sc[j][1] = -1e30f;
                    if (c     > rB) sc[j][2] = -1e30f;
                    if (c + 1 > rB) sc[j][3] = -1e30f;
                }
            }

            // ---- P = exp2(S - C) in f16x2, straight into a-frags ----
            uint32_t pa[4][4];
#pragma unroll
            for (int j = 0; j < 8; j++) {
                __half2 ea = __floats2half2_rn(sc[j][0], sc[j][1]);
                __half2 eb = __floats2half2_rn(sc[j][2], sc[j][3]);
                uint32_t ua = *(uint32_t*)&ea;
                uint32_t ub = *(uint32_t*)&eb;
                asm("ex2.approx.f16x2 %0, %0;" : "+r"(ua));
                asm("ex2.approx.f16x2 %0, %0;" : "+r"(ub));
                const int ss2 = j >> 1, jj = j & 1;
                pa[ss2][jj * 2]     = ua;
                pa[ss2][jj * 2 + 1] = ub;
            }

            // ---- O += P @ V ; l += P @ 1 (ones row at V rows 64..79) ----
#pragma unroll
            for (int ss = 0; ss < 4; ss++) {
#pragma unroll
                for (int nb = 0; nb < 5; nb++) {
                    uint32_t vh4[4];
                    uint32_t boff = (uint32_t)((nb * 16 + brow_in) * ARS + ss * 16 + bk) * 2;
                    ldsm4(vh4, stg + KREG + boff);
                    if (nb < 4) {
                        mma_f16(oc[nb * 2],     pa[ss], &vh4[0]);
                        mma_f16(oc[nb * 2 + 1], pa[ss], &vh4[2]);
                    } else {
                        mma_f16(ocl, pa[ss], &vh4[0]);
                    }
                }
            }
        }
    }

    // ---- epilogue: l in col 64 (quad lane 0); broadcast, normalize ----
    const int qbase = lane & ~3;
    float lA = __shfl_sync(0xffffffffu, ocl[0], qbase);
    float lB = __shfl_sync(0xffffffffu, ocl[2], qbase);
    const float inv0 = 1.0f / lA, inv1 = 1.0f / lB;
    const int rA = qrow0 + g, rB = rA + 8;
    size_t oAoff = ((size_t)b * PS + rA) * PD + h * PHD;
    size_t oBoff = ((size_t)b * PS + rB) * PD + h * PHD;
#pragma unroll
    for (int j = 0; j < 8; j++) {
        int c = j * 8 + 2 * tq;
        __half2 oA = __floats2half2_rn(oc[j][0] * inv0, oc[j][1] * inv0);
        __half2 oB = __floats2half2_rn(oc[j][2] * inv1, oc[j][3] * inv1);
        *(uint32_t*)&Of[oAoff + c] = *(uint32_t*)&oA;
        *(uint32_t*)&Of[oBoff + c] = *(uint32_t*)&oB;
    }
}

// ---------------------------------------------------------------------------
// kernel_launch
// ---------------------------------------------------------------------------
extern "C" void kernel_launch(void* const* d_in, const int* in_sizes, int n_in,
                              void* d_out, int out_size)
{
    const float* query = (const float*)d_in[0];
    const float* key_  = (const float*)d_in[1];
    const float* value = (const float*)d_in[2];
    const float* Wq    = (const float*)d_in[3];
    const float* bq    = (const float*)d_in[4];
    const float* Wk    = (const float*)d_in[5];
    const float* bk    = (const float*)d_in[6];
    const float* Wv    = (const float*)d_in[7];
    const float* bv    = (const float*)d_in[8];
    const float* Wo    = (const float*)d_in[9];
    const float* bo    = (const float*)d_in[10];
    (void)in_sizes; (void)n_in;

    __half *qh, *kh, *vh, *of, *af, *wf;
    cudaGetSymbolAddress((void**)&qh, g_Qh);
    cudaGetSymbolAddress((void**)&kh, g_Kh);
    cudaGetSymbolAddress((void**)&vh, g_Vh);
    cudaGetSymbolAddress((void**)&of, g_Of);
    cudaGetSymbolAddress((void**)&af, g_Af);
    cudaGetSymbolAddress((void**)&wf, g_Wf);

    cudaFuncSetAttribute(qkv_gemm_kernel,
                         cudaFuncAttributeMaxDynamicSharedMemorySize, GEMM_SMEM);
    cudaFuncSetAttribute(out_gemm_kernel,
                         cudaFuncAttributeMaxDynamicSharedMemorySize, GEMM_SMEM);
    cudaFuncSetAttribute(attn_mma_kernel,
                         cudaFuncAttributeMaxDynamicSharedMemorySize, ATTN_SMEM);

    const int nA4 = PM * GK / 4;
    const int nW4 = PD * GK / 4;

    presplitA3_kernel<<<dim3(nA4 / 256, 3), 256>>>(query, key_, value, af, nA4);
    presplitW4_kernel<<<dim3(nW4 / 256, 4), 256>>>(Wq, Wk, Wv, Wo, wf, nW4);

    dim3 ggrid(PD / 128, PM / 128, 3);
    qkv_gemm_kernel<<<ggrid, 256, GEMM_SMEM>>>(af, wf, bq, bk, bv, qh, kh, vh);

    dim3 agrid(PS / 128, PH, PB);
    attn_mma_kernel<<<agrid, 256, ATTN_SMEM>>>(qh, kh, vh, of);

    dim3 ogrid(PD / 128, PM / 128);
    out_gemm_kernel<<<ogrid, 256, GEMM_SMEM>>>(of, wf + (size_t)3 * PD * GK,
                                               bo, (float*)d_out);
}